// round 2
// baseline (speedup 1.0000x reference)
#include <cuda_runtime.h>
#include <math.h>

// Precomputed per-launch coefficients:
//  [0..15]  P = inv(I - kA/2) @ (I + kA/2)   (row-major 4x4)
//  [16..19] b = inv(I - kA/2) @ (k/2 * Bv)
//  [20]     gain_p
__device__ float g_coef[21];

static __device__ __forceinline__ void gauss_inv4(double M[4][4], double Inv[4][4]) {
    // Gauss-Jordan with partial pivoting (4x4), double precision.
    double aug[4][8];
    for (int i = 0; i < 4; i++)
        for (int j = 0; j < 4; j++) {
            aug[i][j] = M[i][j];
            aug[i][4 + j] = (i == j) ? 1.0 : 0.0;
        }
    for (int col = 0; col < 4; col++) {
        int piv = col;
        double best = fabs(aug[col][col]);
        for (int r = col + 1; r < 4; r++) {
            double v = fabs(aug[r][col]);
            if (v > best) { best = v; piv = r; }
        }
        if (piv != col)
            for (int j = 0; j < 8; j++) {
                double t = aug[col][j]; aug[col][j] = aug[piv][j]; aug[piv][j] = t;
            }
        double inv_p = 1.0 / aug[col][col];
        for (int j = 0; j < 8; j++) aug[col][j] *= inv_p;
        for (int r = 0; r < 4; r++) {
            if (r == col) continue;
            double f = aug[r][col];
            for (int j = 0; j < 8; j++) aug[r][j] -= f * aug[col][j];
        }
    }
    for (int i = 0; i < 4; i++)
        for (int j = 0; j < 4; j++)
            Inv[i][j] = aug[i][4 + j];
}

__global__ void moog_setup_kernel(const float* __restrict__ gf,
                                  const float* __restrict__ gr,
                                  const float* __restrict__ gain_p) {
    if (threadIdx.x != 0 || blockIdx.x != 0) return;

    const double R = 0.5;
    const double F = 1000.0;
    const double K = 1.0 / 44100.0;
    const double k2 = 0.5 * K;

    double w = 2.0 * M_PI * (double)__ldg(gf) * F;
    double grd = (double)__ldg(gr);

    double A[4][4] = {
        { -w, 0.0, 0.0, -4.0 * w * grd * R },
        {  w,  -w, 0.0, 0.0 },
        { 0.0,  w,  -w, 0.0 },
        { 0.0, 0.0,  w,  -w }
    };

    double Im[4][4], Ip[4][4];
    for (int i = 0; i < 4; i++)
        for (int j = 0; j < 4; j++) {
            double d = (i == j) ? 1.0 : 0.0;
            Im[i][j] = d - k2 * A[i][j];
            Ip[i][j] = d + k2 * A[i][j];
        }

    double Inv[4][4];
    gauss_inv4(Im, Inv);

    // P = Inv @ Ip
    for (int i = 0; i < 4; i++)
        for (int j = 0; j < 4; j++) {
            double s = 0.0;
            for (int t = 0; t < 4; t++) s += Inv[i][t] * Ip[t][j];
            g_coef[i * 4 + j] = (float)s;
        }
    // b = Inv @ (k2 * w * e0)  = k2*w * Inv[:,0]
    double bk = k2 * w;
    for (int i = 0; i < 4; i++) g_coef[16 + i] = (float)(Inv[i][0] * bk);

    g_coef[20] = __ldg(gain_p);
}

__global__ __launch_bounds__(256) void moog_cell_kernel(
    const float* __restrict__ u_n,
    const float4* __restrict__ x_n1,
    const float* __restrict__ u_n1,
    float* __restrict__ out,      // [y (B) | x (4B) | u (B)]
    int B)
{
    // Load coefficients into registers (L1-resident broadcast after warm-up).
    float c[21];
#pragma unroll
    for (int j = 0; j < 21; j++) c[j] = g_coef[j];

    for (int i = blockIdx.x * blockDim.x + threadIdx.x; i < B;
         i += gridDim.x * blockDim.x) {
        float u  = u_n[i];
        float u1 = u_n1[i];
        float us = u + u1;
        float4 x = x_n1[i];

        float x0 = fmaf(c[0],  x.x, fmaf(c[1],  x.y, fmaf(c[2],  x.z, fmaf(c[3],  x.w, c[16] * us))));
        float x1 = fmaf(c[4],  x.x, fmaf(c[5],  x.y, fmaf(c[6],  x.z, fmaf(c[7],  x.w, c[17] * us))));
        float x2 = fmaf(c[8],  x.x, fmaf(c[9],  x.y, fmaf(c[10], x.z, fmaf(c[11], x.w, c[18] * us))));
        float x3 = fmaf(c[12], x.x, fmaf(c[13], x.y, fmaf(c[14], x.z, fmaf(c[15], x.w, c[19] * us))));

        out[i] = c[20] * x3;                                              // y_n
        reinterpret_cast<float4*>(out + B)[i] = make_float4(x0, x1, x2, x3); // x_n
        out[5 * (size_t)B + i] = u;                                       // u_n passthrough
    }
}

extern "C" void kernel_launch(void* const* d_in, const int* in_sizes, int n_in,
                              void* d_out, int out_size) {
    // Tensor inputs are always the first three (setup_inputs order):
    //   u_n [B], x_n1 [4B], u_n1 [B]
    // Scalar params gf, gr, gain_p are always the LAST three device inputs,
    // regardless of whether the python-int batch_size is materialized.
    const float*  u_n    = (const float*)d_in[0];
    const float4* x_n1   = (const float4*)d_in[1];
    const float*  u_n1   = (const float*)d_in[2];
    const float*  gf     = (const float*)d_in[n_in - 3];
    const float*  gr     = (const float*)d_in[n_in - 2];
    const float*  gain_p = (const float*)d_in[n_in - 1];

    int B = in_sizes[0];
    float* out = (float*)d_out;

    moog_setup_kernel<<<1, 32>>>(gf, gr, gain_p);
    int threads = 256;
    int blocks = (B + threads - 1) / threads;
    moog_cell_kernel<<<blocks, threads>>>(u_n, x_n1, u_n1, out, B);
}

// round 3
// speedup vs baseline: 1.1307x; 1.1307x over previous
#include <cuda_runtime.h>
#include <math.h>

// a = (K/2) * w = (K/2) * 2*pi*gf*F = pi * F * K * gf,  F=1000, K=1/44100
#define A_PER_GF 0.07123792533241012f   // pi*1000/44100

struct Coef {
    float p[16];   // P = 2*inv(I - kA/2) - I, row-major
    float b[4];    // b = inv(I - kA/2) @ (k/2 * Bv)
    float gain;
};

static __device__ __forceinline__ Coef make_coef(float gf, float gr, float gain_p) {
    // M = I - (k/2)A = [[d,0,0,c],[-s,d,0,0],[0,-s,d,0],[0,0,-s,d]]
    float a = A_PER_GF * gf;
    float s = a;
    float d = 1.0f + a;
    float c = 2.0f * a * gr;          // (k/2)*4*w*gr*R, R=0.5

    float d2 = d * d, d3 = d2 * d;
    float s2 = s * s, s3 = s2 * s;
    float invDet = 1.0f / (d3 * d + c * s3);
    float invd = 1.0f / d;

    float inv[4][4];
    // row 0
    inv[0][0] =  d3 * invDet;
    inv[0][1] = -c * s2 * invDet;
    inv[0][2] = -c * s * d * invDet;
    inv[0][3] = -c * d2 * invDet;
    // row i = (s*row_{i-1} + e_i) / d
#pragma unroll
    for (int i = 1; i < 4; i++)
#pragma unroll
        for (int j = 0; j < 4; j++)
            inv[i][j] = (s * inv[i - 1][j] + ((i == j) ? 1.0f : 0.0f)) * invd;

    Coef k;
#pragma unroll
    for (int i = 0; i < 4; i++) {
#pragma unroll
        for (int j = 0; j < 4; j++)
            k.p[i * 4 + j] = 2.0f * inv[i][j] - ((i == j) ? 1.0f : 0.0f);
        k.b[i] = a * inv[i][0];       // Inv @ ((k/2)*w * e0)
    }
    k.gain = gain_p;
    return k;
}

static __device__ __forceinline__ float4 step(const Coef& k, float4 x, float us,
                                              float& y_out) {
    float x0 = fmaf(k.p[0],  x.x, fmaf(k.p[1],  x.y, fmaf(k.p[2],  x.z, fmaf(k.p[3],  x.w, k.b[0] * us))));
    float x1 = fmaf(k.p[4],  x.x, fmaf(k.p[5],  x.y, fmaf(k.p[6],  x.z, fmaf(k.p[7],  x.w, k.b[1] * us))));
    float x2 = fmaf(k.p[8],  x.x, fmaf(k.p[9],  x.y, fmaf(k.p[10], x.z, fmaf(k.p[11], x.w, k.b[2] * us))));
    float x3 = fmaf(k.p[12], x.x, fmaf(k.p[13], x.y, fmaf(k.p[14], x.z, fmaf(k.p[15], x.w, k.b[3] * us))));
    y_out = k.gain * x3;
    return make_float4(x0, x1, x2, x3);
}

// Vectorized: each thread handles 4 consecutive batch elements (B % 4 == 0).
__global__ __launch_bounds__(256) void moog_cell_v4_kernel(
    const float4* __restrict__ u_n,     // B/4 float4
    const float4* __restrict__ x_n1,    // B float4 (one per element)
    const float4* __restrict__ u_n1,    // B/4 float4
    float* __restrict__ out,            // [y (B) | x (4B) | u (B)]
    int B,
    const float* __restrict__ gf_p,
    const float* __restrict__ gr_p,
    const float* __restrict__ gain_pp)
{
    const Coef k = make_coef(__ldg(gf_p), __ldg(gr_p), __ldg(gain_pp));

    int n4 = B >> 2;
    int t = blockIdx.x * blockDim.x + threadIdx.x;
    if (t >= n4) return;

    float4 u4  = u_n[t];
    float4 u14 = u_n1[t];
    float4 xa = x_n1[4 * t + 0];
    float4 xb = x_n1[4 * t + 1];
    float4 xc = x_n1[4 * t + 2];
    float4 xd = x_n1[4 * t + 3];

    float4 y4;
    float4 ra = step(k, xa, u4.x + u14.x, y4.x);
    float4 rb = step(k, xb, u4.y + u14.y, y4.y);
    float4 rc = step(k, xc, u4.z + u14.z, y4.z);
    float4 rd = step(k, xd, u4.w + u14.w, y4.w);

    float4* ybase = reinterpret_cast<float4*>(out);
    float4* xbase = reinterpret_cast<float4*>(out + B);
    float4* ubase = reinterpret_cast<float4*>(out + 5 * (size_t)B);

    ybase[t] = y4;
    xbase[4 * t + 0] = ra;
    xbase[4 * t + 1] = rb;
    xbase[4 * t + 2] = rc;
    xbase[4 * t + 3] = rd;
    ubase[t] = u4;    // u_n passthrough
}

// Scalar fallback for B % 4 != 0 (not expected for this problem).
__global__ __launch_bounds__(256) void moog_cell_scalar_kernel(
    const float* __restrict__ u_n,
    const float4* __restrict__ x_n1,
    const float* __restrict__ u_n1,
    float* __restrict__ out,
    int B,
    const float* __restrict__ gf_p,
    const float* __restrict__ gr_p,
    const float* __restrict__ gain_pp)
{
    const Coef k = make_coef(__ldg(gf_p), __ldg(gr_p), __ldg(gain_pp));
    int i = blockIdx.x * blockDim.x + threadIdx.x;
    if (i >= B) return;
    float u = u_n[i];
    float y;
    float4 r = step(k, x_n1[i], u + u_n1[i], y);
    out[i] = y;
    reinterpret_cast<float4*>(out + B)[i] = r;
    out[5 * (size_t)B + i] = u;
}

extern "C" void kernel_launch(void* const* d_in, const int* in_sizes, int n_in,
                              void* d_out, int out_size) {
    const float* u_n    = (const float*)d_in[0];
    const float4* x_n1  = (const float4*)d_in[1];
    const float* u_n1   = (const float*)d_in[2];
    // scalars are the last three device inputs regardless of batch_size materialization
    const float* gf     = (const float*)d_in[n_in - 3];
    const float* gr     = (const float*)d_in[n_in - 2];
    const float* gain_p = (const float*)d_in[n_in - 1];

    int B = in_sizes[0];
    float* out = (float*)d_out;

    if ((B & 3) == 0) {
        int n4 = B >> 2;
        int threads = 256;
        int blocks = (n4 + threads - 1) / threads;
        moog_cell_v4_kernel<<<blocks, threads>>>(
            (const float4*)u_n, x_n1, (const float4*)u_n1, out, B, gf, gr, gain_p);
    } else {
        int threads = 256;
        int blocks = (B + threads - 1) / threads;
        moog_cell_scalar_kernel<<<blocks, threads>>>(
            u_n, x_n1, u_n1, out, B, gf, gr, gain_p);
    }
}